// round 16
// baseline (speedup 1.0000x reference)
#include <cuda_runtime.h>
#include <math.h>

// Problem constants (fixed shapes from setup_inputs)
#define NB 256
#define NJ 24
#define TDIM 1024
#define NF 8
#define NBLOCKS (NB * NF)            // 2048: one block per (batch, frame)
// loss scale: 1 / (B * F * J * 3)
#define LOSS_SCALE (1.0f / 147456.0f)

// Ancestor path (root -> j, inclusive) per joint, padded; LEN = path length.
__device__ __constant__ int c_PATH[NJ][9] = {
    {0,0,0,0,0,0,0,0,0},          // 0
    {0,1,0,0,0,0,0,0,0},          // 1
    {0,2,0,0,0,0,0,0,0},          // 2
    {0,3,0,0,0,0,0,0,0},          // 3
    {0,1,4,0,0,0,0,0,0},          // 4
    {0,2,5,0,0,0,0,0,0},          // 5
    {0,3,6,0,0,0,0,0,0},          // 6
    {0,1,4,7,0,0,0,0,0},          // 7
    {0,2,5,8,0,0,0,0,0},          // 8
    {0,3,6,9,0,0,0,0,0},          // 9
    {0,1,4,7,10,0,0,0,0},         // 10
    {0,2,5,8,11,0,0,0,0},         // 11
    {0,3,6,9,12,0,0,0,0},         // 12
    {0,3,6,9,13,0,0,0,0},         // 13
    {0,3,6,9,14,0,0,0,0},         // 14
    {0,3,6,9,12,15,0,0,0},        // 15
    {0,3,6,9,13,16,0,0,0},        // 16
    {0,3,6,9,14,17,0,0,0},        // 17
    {0,3,6,9,13,16,18,0,0},       // 18
    {0,3,6,9,14,17,19,0,0},       // 19
    {0,3,6,9,13,16,18,20,0},      // 20
    {0,3,6,9,14,17,19,21,0},      // 21
    {0,3,6,9,13,16,18,20,22},     // 22
    {0,3,6,9,14,17,19,21,23}      // 23
};
__device__ __constant__ int c_LEN[NJ] = {
    1,2,2,2,3,3,3,4,4,4,5,5,5,5,5,6,6,6,7,7,8,8,9,9
};
// Parent of each joint (index 0 unused for root).
__device__ __constant__ int c_PAR[NJ] = {
    0,0,0,0, 1,2,3, 4,5,6, 7,8,9, 9,9, 12,13,14, 16,17, 18,19, 20,21
};
// linspace(0, 1023, 8).astype(int32)
__device__ __constant__ int c_FIDX[NF] = {0,146,292,438,584,730,876,1023};
// Joints whose LOCAL rotation is consumed (appear as a parent). Leaves
// {10,11,15,22,23} are dead: their gq is computed by the ref but never used.
__device__ __constant__ int c_NEED[NJ] = {
    1,1,1,1, 1,1,1,1, 1,1, 0,0, 1,1,1, 0, 1,1,1,1, 1,1, 0,0
};

// Device-global reduction state (zero-initialized at module load; each launch
// leaves it back at zero -> deterministic across graph replays).
__device__ float        g_acc = 0.0f;
__device__ unsigned int g_cnt = 0u;

struct Quat { float w, x, y, z; };

// Single-MUFU approximations (rel err ~3e-7; loss tolerance is 1e-3).
__device__ __forceinline__ float rsqrt_a(float x) {
    float r; asm("rsqrt.approx.f32 %0, %1;" : "=f"(r) : "f"(x)); return r;
}
__device__ __forceinline__ float sqrt_a(float x) {
    float r; asm("sqrt.approx.f32 %0, %1;" : "=f"(r) : "f"(x)); return r;
}
__device__ __forceinline__ float rcp_a(float x) {
    float r; asm("rcp.approx.f32 %0, %1;" : "=f"(r) : "f"(x)); return r;
}

__device__ __forceinline__ Quat qmul(const Quat a, const Quat b) {
    Quat r;
    r.w = a.w*b.w - a.x*b.x - a.y*b.y - a.z*b.z;
    r.x = a.w*b.x + a.x*b.w + a.y*b.z - a.z*b.y;
    r.y = a.w*b.y - a.x*b.z + a.y*b.w + a.z*b.x;
    r.z = a.w*b.z + a.x*b.y - a.y*b.x + a.z*b.w;
    return r;
}

// rotate v by quaternion q (wxyz):  v + w*t + cross(xyz, t),  t = 2*cross(xyz, v)
__device__ __forceinline__ void qrot(const Quat q, float vx, float vy, float vz,
                                     float& ox, float& oy, float& oz) {
    float tx = 2.0f * (q.y*vz - q.z*vy);
    float ty = 2.0f * (q.z*vx - q.x*vz);
    float tz = 2.0f * (q.x*vy - q.y*vx);
    ox = vx + q.w*tx + (q.y*tz - q.z*ty);
    oy = vy + q.w*ty + (q.z*tx - q.x*tz);
    oz = vz + q.w*tz + (q.x*ty - q.y*tx);
}

// 6d -> quaternion: Gram-Schmidt + branchless pytorch3d select, all normalizations
// via single-MUFU approx ops, k-select via SEL (no divergent branches).
__device__ __forceinline__ Quat quat_from_6d(const float v[6]) {
    float a1x = v[0], a1y = v[1], a1z = v[2];
    float a2x = v[3], a2y = v[4], a2z = v[5];
    float n1sq = a1x*a1x + a1y*a1y + a1z*a1z;
    float i1 = rsqrt_a(fmaxf(n1sq, 1e-16f));
    float b1x = a1x*i1, b1y = a1y*i1, b1z = a1z*i1;
    float d = b1x*a2x + b1y*a2y + b1z*a2z;
    float ux = a2x - d*b1x, uy = a2y - d*b1y, uz = a2z - d*b1z;
    float n2sq = ux*ux + uy*uy + uz*uz;
    float i2 = rsqrt_a(fmaxf(n2sq, 1e-16f));
    float b2x = ux*i2, b2y = uy*i2, b2z = uz*i2;
    float b3x = b1y*b2z - b1z*b2y;
    float b3y = b1z*b2x - b1x*b2z;
    float b3z = b1x*b2y - b1y*b2x;
    // matrix rows: b1, b2, b3
    float m00 = b1x, m01 = b1y, m02 = b1z;
    float m10 = b2x, m11 = b2y, m12 = b2z;
    float m20 = b3x, m21 = b3y, m22 = b3z;

    float qa0 = sqrt_a(fmaxf(1.0f + m00 + m11 + m22, 0.0f));
    float qa1 = sqrt_a(fmaxf(1.0f + m00 - m11 - m22, 0.0f));
    float qa2 = sqrt_a(fmaxf(1.0f - m00 + m11 - m22, 0.0f));
    float qa3 = sqrt_a(fmaxf(1.0f - m00 - m11 + m22, 0.0f));

    // first-argmax (strict >) — compiles to FSETP+SEL, no branches
    int k = 0; float best = qa0;
    if (qa1 > best) { k = 1; best = qa1; }
    if (qa2 > best) { k = 2; best = qa2; }
    if (qa3 > best) { k = 3; best = qa3; }

    const float s21m = m21 - m12, s02m = m02 - m20, s10m = m10 - m01;
    const float s10p = m10 + m01, s02p = m02 + m20, s12p = m12 + m21;

    float w = (k == 0) ? qa0*qa0 : (k == 1) ? s21m : (k == 2) ? s02m : s10m;
    float x = (k == 0) ? s21m : (k == 1) ? qa1*qa1 : (k == 2) ? s10p : s02p;
    float y = (k == 0) ? s02m : (k == 1) ? s10p : (k == 2) ? qa2*qa2 : s12p;
    float z = (k == 0) ? s10m : (k == 1) ? s02p : (k == 2) ? s12p : qa3*qa3;

    float inv = 0.5f * rcp_a(fmaxf(best, 0.1f));
    Quat q; q.w = w*inv; q.x = x*inv; q.y = y*inv; q.z = z*inv;
    return q;
}

// One block per (batch, frame): 2048 blocks x 64 threads (48 active).
// thread = (side s in 0..1) x (joint j in 0..23). ~14-18 blocks/SM resident
// -> ~28+ warps/SM, cheap 2-warp barriers, deep cross-block overlap.
//   phase 1: needed (s,j) threads gather 6 scattered scalars -> local quat -> smem
//   phase 2: needed threads fold global quat along ancestor path -> smem
//   phase 3a: edge qrot per (s, j>=1): e = qrot(gq[s][parent(j)], off[j]) -> smem
//   phase 3b: s==0 threads sum edge diffs along path, square
//   reduce:  2-warp shuffle reduce; one atomic per block into device-global acc
__global__ void __launch_bounds__(64, 16)
fk_loss_kernel(const float* __restrict__ pred,
               const float* __restrict__ targ,
               const float* __restrict__ offsets,
               float* __restrict__ out) {
    __shared__ float s_lq[2][NJ][4];
    __shared__ float s_gq[2][NJ][4];
    __shared__ float s_edge[2][NJ][3];
    __shared__ float s_part[2];

    const int tid = threadIdx.x;
    const int b   = blockIdx.x >> 3;
    const int f   = blockIdx.x & 7;
    const int s   = tid / NJ;            // 0 = pred, 1 = target (tid >= 48 idle)
    const int j   = tid - s * NJ;
    const int fi  = c_FIDX[f];
    const bool active = (tid < 2 * NJ);
    const int need = active ? c_NEED[j] : 0;

    // ---- phase 1: local quats (needed joints only: dead leaves skipped) ----
    if (need) {
        const float* __restrict__ ptr = s ? targ : pred;
        const int base = ((b * NJ + j) * 6) * TDIM + fi;
        float v[6];
#pragma unroll
        for (int c = 0; c < 6; ++c)
            v[c] = __ldg(ptr + base + c * TDIM);
        Quat q = quat_from_6d(v);
        s_lq[s][j][0] = q.w; s_lq[s][j][1] = q.x;
        s_lq[s][j][2] = q.y; s_lq[s][j][3] = q.z;
    }
    __syncthreads();

    // ---- phase 2: global quats (left-fold along ancestor path, ref FP order) ----
    if (need) {
        Quat q = { s_lq[s][0][0], s_lq[s][0][1], s_lq[s][0][2], s_lq[s][0][3] };
        const int len = c_LEN[j];
        for (int d2 = 1; d2 < len; ++d2) {
            const int a = c_PATH[j][d2];
            Quat l = { s_lq[s][a][0], s_lq[s][a][1], s_lq[s][a][2], s_lq[s][a][3] };
            q = qmul(q, l);
        }
        s_gq[s][j][0] = q.w; s_gq[s][j][1] = q.x;
        s_gq[s][j][2] = q.y; s_gq[s][j][3] = q.z;
    }
    __syncthreads();

    // ---- phase 3a: one qrot per (s, edge j>=1): e = qrot(gq[parent(j)], off[j]) ----
    if (active && j >= 1) {
        const int p = c_PAR[j];
        const float ox = __ldg(offsets + j * 3 + 0);
        const float oy = __ldg(offsets + j * 3 + 1);
        const float oz = __ldg(offsets + j * 3 + 2);
        Quat qp = { s_gq[s][p][0], s_gq[s][p][1], s_gq[s][p][2], s_gq[s][p][3] };
        float rx, ry, rz;
        qrot(qp, ox, oy, oz, rx, ry, rz);
        s_edge[s][j][0] = rx; s_edge[s][j][1] = ry; s_edge[s][j][2] = rz;
    }
    __syncthreads();

    // ---- phase 3b: position diff = sum of edge diffs along path; square ----
    float acc = 0.0f;
    if (active && s == 0) {   // 24 threads: one per joint
        float dx = 0.f, dy = 0.f, dz = 0.f;
        const int len = c_LEN[j];
        for (int d2 = 1; d2 < len; ++d2) {
            const int a = c_PATH[j][d2];
            dx += s_edge[0][a][0] - s_edge[1][a][0];
            dy += s_edge[0][a][1] - s_edge[1][a][1];
            dz += s_edge[0][a][2] - s_edge[1][a][2];
        }
        acc = dx*dx + dy*dy + dz*dz;
    }

    // ---- block reduce: 2-warp shuffle -> smem -> thread 0 atomic ----
#pragma unroll
    for (int o = 16; o > 0; o >>= 1)
        acc += __shfl_down_sync(0xffffffffu, acc, o);
    const int wid  = tid >> 5;
    if ((tid & 31) == 0) s_part[wid] = acc;
    __syncthreads();

    // ---- grid reduce: device-global accumulator; last block writes + resets ----
    if (tid == 0) {
        float total = s_part[0] + s_part[1];
        atomicAdd(&g_acc, total);
        __threadfence();
        unsigned int old = atomicAdd(&g_cnt, 1u);
        if (old == NBLOCKS - 1u) {            // last block to finish
            __threadfence();
            float tot = *((volatile float*)&g_acc);
            out[0] = tot * LOSS_SCALE;
            // reset for next replay (deterministic state)
            *((volatile float*)&g_acc) = 0.0f;
            __threadfence();
            *((volatile unsigned int*)&g_cnt) = 0u;
        }
    }
}

extern "C" void kernel_launch(void* const* d_in, const int* in_sizes, int n_in,
                              void* d_out, int out_size) {
    const float* pred    = (const float*)d_in[0];   // (256, 24, 6, 1024)
    const float* targ    = (const float*)d_in[1];   // (256, 24, 6, 1024)
    // d_in[2] = root_translation — cancels in the position diff, never read
    const float* offsets = (const float*)d_in[3];   // (24, 3)
    float* out = (float*)d_out;

    fk_loss_kernel<<<NBLOCKS, 64>>>(pred, targ, offsets, out);
}

// round 17
// speedup vs baseline: 1.3602x; 1.3602x over previous
#include <cuda_runtime.h>
#include <math.h>

// Problem constants (fixed shapes from setup_inputs)
#define NB 256
#define NJ 24
#define TDIM 1024
#define NF 8
// loss scale: 1 / (B * F * J * 3)
#define LOSS_SCALE (1.0f / 147456.0f)

// need bitmask: joints whose local rotation is consumed (appear as a parent).
// bits 0-9, 12-14, 16-21 set; leaves {10,11,15,22,23} dead.
#define NEED_MASK 0x3F73FFu
// path length per joint, packed 4 bits each (j0..15 in LO, j16..23 in HI).
#define LEN_LO 0x6555554443332221ull
#define LEN_HI 0x99887766ull

// Ancestor path (root -> j), packed 5 bits per level in a uint64.
// level d lives at bits [5d, 5d+5). One divergent LDC per thread, ONCE.
__device__ __constant__ unsigned long long c_PATH64[NJ] = {
    0x0ull,            // 0:  {0}
    0x20ull,           // 1:  {0,1}
    0x40ull,           // 2:  {0,2}
    0x60ull,           // 3:  {0,3}
    0x1020ull,         // 4:  {0,1,4}
    0x1440ull,         // 5:  {0,2,5}
    0x1860ull,         // 6:  {0,3,6}
    0x39020ull,        // 7:  {0,1,4,7}
    0x41440ull,        // 8:  {0,2,5,8}
    0x49860ull,        // 9:  {0,3,6,9}
    0xA39020ull,       // 10: {0,1,4,7,10}
    0xB41440ull,       // 11: {0,2,5,8,11}
    0xC49860ull,       // 12: {0,3,6,9,12}
    0xD49860ull,       // 13: {0,3,6,9,13}
    0xE49860ull,       // 14: {0,3,6,9,14}
    0x1EC49860ull,     // 15: {0,3,6,9,12,15}
    0x20D49860ull,     // 16: {0,3,6,9,13,16}
    0x22E49860ull,     // 17: {0,3,6,9,14,17}
    0x4A0D49860ull,    // 18: {0,3,6,9,13,16,18}
    0x4E2E49860ull,    // 19: {0,3,6,9,14,17,19}
    0xA4A0D49860ull,   // 20: {0,3,6,9,13,16,18,20}
    0xACE2E49860ull,   // 21: {0,3,6,9,14,17,19,21}
    0x16A4A0D49860ull, // 22: {0,3,6,9,13,16,18,20,22}
    0x17ACE2E49860ull  // 23: {0,3,6,9,14,17,19,21,23}
};

// Device-global reduction state (zero-initialized at module load; each launch
// leaves it back at zero -> deterministic across graph replays).
__device__ float        g_acc = 0.0f;
__device__ unsigned int g_cnt = 0u;

struct Quat { float w, x, y, z; };

// Single-MUFU approximations (rel err ~3e-7; loss tolerance is 1e-3).
__device__ __forceinline__ float rsqrt_a(float x) {
    float r; asm("rsqrt.approx.f32 %0, %1;" : "=f"(r) : "f"(x)); return r;
}
__device__ __forceinline__ float sqrt_a(float x) {
    float r; asm("sqrt.approx.f32 %0, %1;" : "=f"(r) : "f"(x)); return r;
}
__device__ __forceinline__ float rcp_a(float x) {
    float r; asm("rcp.approx.f32 %0, %1;" : "=f"(r) : "f"(x)); return r;
}

__device__ __forceinline__ Quat qmul(const Quat a, const Quat b) {
    Quat r;
    r.w = a.w*b.w - a.x*b.x - a.y*b.y - a.z*b.z;
    r.x = a.w*b.x + a.x*b.w + a.y*b.z - a.z*b.y;
    r.y = a.w*b.y - a.x*b.z + a.y*b.w + a.z*b.x;
    r.z = a.w*b.z + a.x*b.y - a.y*b.x + a.z*b.w;
    return r;
}

// rotate v by quaternion q (wxyz):  v + w*t + cross(xyz, t),  t = 2*cross(xyz, v)
__device__ __forceinline__ void qrot(const Quat q, float vx, float vy, float vz,
                                     float& ox, float& oy, float& oz) {
    float tx = 2.0f * (q.y*vz - q.z*vy);
    float ty = 2.0f * (q.z*vx - q.x*vz);
    float tz = 2.0f * (q.x*vy - q.y*vx);
    ox = vx + q.w*tx + (q.y*tz - q.z*ty);
    oy = vy + q.w*ty + (q.z*tx - q.x*tz);
    oz = vz + q.w*tz + (q.x*ty - q.y*tx);
}

// 6d -> quaternion: Gram-Schmidt + branchless pytorch3d select, all normalizations
// via single-MUFU approx ops, k-select via SEL (no divergent branches).
__device__ __forceinline__ Quat quat_from_6d(const float v[6]) {
    float a1x = v[0], a1y = v[1], a1z = v[2];
    float a2x = v[3], a2y = v[4], a2z = v[5];
    float n1sq = a1x*a1x + a1y*a1y + a1z*a1z;
    float i1 = rsqrt_a(fmaxf(n1sq, 1e-16f));
    float b1x = a1x*i1, b1y = a1y*i1, b1z = a1z*i1;
    float d = b1x*a2x + b1y*a2y + b1z*a2z;
    float ux = a2x - d*b1x, uy = a2y - d*b1y, uz = a2z - d*b1z;
    float n2sq = ux*ux + uy*uy + uz*uz;
    float i2 = rsqrt_a(fmaxf(n2sq, 1e-16f));
    float b2x = ux*i2, b2y = uy*i2, b2z = uz*i2;
    float b3x = b1y*b2z - b1z*b2y;
    float b3y = b1z*b2x - b1x*b2z;
    float b3z = b1x*b2y - b1y*b2x;
    // matrix rows: b1, b2, b3
    float m00 = b1x, m01 = b1y, m02 = b1z;
    float m10 = b2x, m11 = b2y, m12 = b2z;
    float m20 = b3x, m21 = b3y, m22 = b3z;

    float qa0 = sqrt_a(fmaxf(1.0f + m00 + m11 + m22, 0.0f));
    float qa1 = sqrt_a(fmaxf(1.0f + m00 - m11 - m22, 0.0f));
    float qa2 = sqrt_a(fmaxf(1.0f - m00 + m11 - m22, 0.0f));
    float qa3 = sqrt_a(fmaxf(1.0f - m00 - m11 + m22, 0.0f));

    // first-argmax (strict >) — compiles to FSETP+SEL, no branches
    int k = 0; float best = qa0;
    if (qa1 > best) { k = 1; best = qa1; }
    if (qa2 > best) { k = 2; best = qa2; }
    if (qa3 > best) { k = 3; best = qa3; }

    const float s21m = m21 - m12, s02m = m02 - m20, s10m = m10 - m01;
    const float s10p = m10 + m01, s02p = m02 + m20, s12p = m12 + m21;

    float w = (k == 0) ? qa0*qa0 : (k == 1) ? s21m : (k == 2) ? s02m : s10m;
    float x = (k == 0) ? s21m : (k == 1) ? qa1*qa1 : (k == 2) ? s10p : s02p;
    float y = (k == 0) ? s02m : (k == 1) ? s10p : (k == 2) ? qa2*qa2 : s12p;
    float z = (k == 0) ? s10m : (k == 1) ? s02p : (k == 2) ? s12p : qa3*qa3;

    float inv = 0.5f * rcp_a(fmaxf(best, 0.1f));
    Quat q; q.w = w*inv; q.x = x*inv; q.y = y*inv; q.z = z*inv;
    return q;
}

// One block per batch b. 384 threads = (f 0..7) x (s 0..1) x (j 0..23).
// ALL per-joint tables are ALU (bitmask/packed immediates) or a single packed
// uint64 path register -> no divergent LDC replay storms in the hot loops.
__global__ void __launch_bounds__(384, 2)
fk_loss_kernel(const float* __restrict__ pred,
               const float* __restrict__ targ,
               const float* __restrict__ offsets,
               float* __restrict__ out) {
    __shared__ float s_lq[NF][2][NJ][4];
    __shared__ float s_gq[NF][2][NJ][4];
    __shared__ float s_edge[NF][2][NJ][3];
    __shared__ float s_part[12];

    const int tid = threadIdx.x;
    const int b   = blockIdx.x;
    const int f   = tid / 48;
    const int r   = tid - f * 48;
    const int s   = r / NJ;          // 0 = pred, 1 = target
    const int j   = r - s * NJ;
    const int fi  = (f * 1023) / 7;  // == linspace(0,1023,8)[f], pure ALU
    const int need = (NEED_MASK >> j) & 1;
    const int len  = (j < 16) ? (int)((LEN_LO >> (4 * j)) & 15)
                              : (int)((LEN_HI >> (4 * (j - 16))) & 15);
    const unsigned long long pth = c_PATH64[j];   // single divergent LDC, once

    // ---- phase 1: local quats (needed joints only: dead leaves skipped) ----
    if (need) {
        const float* __restrict__ ptr = s ? targ : pred;
        const int base = ((b * NJ + j) * 6) * TDIM + fi;
        float v[6];
#pragma unroll
        for (int c = 0; c < 6; ++c)
            v[c] = __ldg(ptr + base + c * TDIM);
        Quat q = quat_from_6d(v);
        s_lq[f][s][j][0] = q.w; s_lq[f][s][j][1] = q.x;
        s_lq[f][s][j][2] = q.y; s_lq[f][s][j][3] = q.z;
    }
    __syncthreads();

    // ---- phase 2: global quats (left-fold along ancestor path, ref FP order) ----
    if (need) {
        Quat q = { s_lq[f][s][0][0], s_lq[f][s][0][1], s_lq[f][s][0][2], s_lq[f][s][0][3] };
        for (int d2 = 1; d2 < len; ++d2) {
            const int a = (int)((pth >> (5 * d2)) & 31);
            Quat l = { s_lq[f][s][a][0], s_lq[f][s][a][1], s_lq[f][s][a][2], s_lq[f][s][a][3] };
            q = qmul(q, l);
        }
        s_gq[f][s][j][0] = q.w; s_gq[f][s][j][1] = q.x;
        s_gq[f][s][j][2] = q.y; s_gq[f][s][j][3] = q.z;
    }
    __syncthreads();

    // ---- phase 3a: one qrot per (s, edge j>=1): e = qrot(gq[parent(j)], off[j]) ----
    if (j >= 1) {
        const int p = (int)((pth >> (5 * (len - 2))) & 31);   // parent(j)
        const float ox = __ldg(offsets + j * 3 + 0);
        const float oy = __ldg(offsets + j * 3 + 1);
        const float oz = __ldg(offsets + j * 3 + 2);
        Quat qp = { s_gq[f][s][p][0], s_gq[f][s][p][1], s_gq[f][s][p][2], s_gq[f][s][p][3] };
        float rx, ry, rz;
        qrot(qp, ox, oy, oz, rx, ry, rz);
        s_edge[f][s][j][0] = rx; s_edge[f][s][j][1] = ry; s_edge[f][s][j][2] = rz;
    }
    __syncthreads();

    // ---- phase 3b: position diff = sum of edge diffs along path; square ----
    float acc = 0.0f;
    if (s == 0) {   // 192 threads: one per (f, j)
        float dx = 0.f, dy = 0.f, dz = 0.f;
        for (int d2 = 1; d2 < len; ++d2) {
            const int a = (int)((pth >> (5 * d2)) & 31);
            dx += s_edge[f][0][a][0] - s_edge[f][1][a][0];
            dy += s_edge[f][0][a][1] - s_edge[f][1][a][1];
            dz += s_edge[f][0][a][2] - s_edge[f][1][a][2];
        }
        acc = dx*dx + dy*dy + dz*dz;
    }

    // ---- block reduce: warp shuffle -> smem partials -> thread 0 ----
#pragma unroll
    for (int o = 16; o > 0; o >>= 1)
        acc += __shfl_down_sync(0xffffffffu, acc, o);
    const int wid  = tid >> 5;
    const int lane = tid & 31;
    if (lane == 0) s_part[wid] = acc;
    __syncthreads();

    // ---- grid reduce: device-global accumulator; last block writes + resets ----
    if (tid == 0) {
        float total = 0.0f;
#pragma unroll
        for (int w = 0; w < 12; ++w) total += s_part[w];
        atomicAdd(&g_acc, total);
        __threadfence();
        unsigned int old = atomicAdd(&g_cnt, 1u);
        if (old == NB - 1u) {                 // last block to finish
            __threadfence();
            float tot = *((volatile float*)&g_acc);
            out[0] = tot * LOSS_SCALE;
            // reset for next replay (deterministic state)
            *((volatile float*)&g_acc) = 0.0f;
            __threadfence();
            *((volatile unsigned int*)&g_cnt) = 0u;
        }
    }
}

extern "C" void kernel_launch(void* const* d_in, const int* in_sizes, int n_in,
                              void* d_out, int out_size) {
    const float* pred    = (const float*)d_in[0];   // (256, 24, 6, 1024)
    const float* targ    = (const float*)d_in[1];   // (256, 24, 6, 1024)
    // d_in[2] = root_translation — cancels in the position diff, never read
    const float* offsets = (const float*)d_in[3];   // (24, 3)
    float* out = (float*)d_out;

    fk_loss_kernel<<<NB, 384>>>(pred, targ, offsets, out);
}